// round 8
// baseline (speedup 1.0000x reference)
#include <cuda_runtime.h>

// Ray-marched volumetric sphere, 1024x1024 pixels, 4 pixels/thread,
// fused 4-wide march loop with second-difference recurrences.
// in[0] = scene (4 f32: cx, cy, cz, radius)
// in[1] = dirs  (1024*1024*3 f32, normalized)
// out   = pixels (1024*1024*3 f32)

#define LOG2E    1.4426950408889634f
#define K_LIGHT  (-1.2f * LOG2E)   // exp2 coeff: DENSITY*(SCAT+ABS) = 1.2
#define K_SIGMA  (-0.6f * LOG2E)   // exp2 coeff: SIGMA = 0.6

__device__ __forceinline__ float fsqrt_approx(float x) {
    float r; asm("sqrt.approx.f32 %0, %1;" : "=f"(r) : "f"(x)); return r;
}
__device__ __forceinline__ float fexp2_approx(float x) {
    float r; asm("ex2.approx.f32 %0, %1;" : "=f"(r) : "f"(x)); return r;
}

__global__ __launch_bounds__(128) void raymarch_kernel(
    const float* __restrict__ scene,
    const float4* __restrict__ dirs4,
    float4* __restrict__ out4,
    int nthreads)
{
    const int t = blockIdx.x * 128 + threadIdx.x;
    if (t >= nthreads) return;

    const float cx = __ldg(scene + 0);
    const float cy = __ldg(scene + 1);
    const float cz = __ldg(scene + 2);
    const float radius = __ldg(scene + 3);
    const float r2 = radius * radius;

    // RO = (0,0,3)
    const float ocx = -cx, ocy = -cy, ocz = 3.0f - cz;
    const float oc2 = ocx * ocx + ocy * ocy + ocz * ocz;

    const float4 d0 = dirs4[3 * t + 0];
    const float4 d1 = dirs4[3 * t + 1];
    const float4 d2 = dirs4[3 * t + 2];

    float rx[4] = {d0.x, d0.w, d1.z, d2.y};
    float ry[4] = {d0.y, d1.x, d1.w, d2.z};
    float rz[4] = {d0.z, d1.y, d2.x, d2.w};

    // Per-pixel marching state (second-difference recurrences)
    float h[4], u1[4], u2[4], nkp[4], dnk[4], acc[4], nsf[4], stp[4], nsv[4];
    bool  hit[4];
    float maxns = 0.0f;

    #pragma unroll
    for (int j = 0; j < 4; j++) {
        // |rd| == 1: half-b quadratic
        const float hb = rx[j] * ocx + ry[j] * ocy + rz[j] * ocz;
        const float disc = hb * hb - (oc2 - r2);
        const float sq = fsqrt_approx(fmaxf(disc, 0.0f));   // NaN-free
        const float x2 = sq - hb;
        const bool hj = (disc >= 0.0f) && (x2 >= 0.0f);

        const float t0 = fmaxf(-sq - hb, 0.0f);
        const float seg = x2 - t0;
        const float ns = ceilf(seg * 5.0f);                 // seg / 0.2
        const float st = __fdividef(seg, fmaxf(ns, 1.0f));
        const float nf = hj ? fminf(ns, 12.0f) : 0.0f;
        maxns = fmaxf(maxns, nf);

        // position at k=0: pc = oc + (x2 - 0.5*st)*rd; per-step delta = st*rd
        const float ti = x2 - 0.5f * st;
        const float X0 = ocx + ti * rx[j];
        const float Y0 = ocy + ti * ry[j];
        const float Z0 = ocz + ti * rz[j];
        const float dx = st * rx[j], dy = st * ry[j], dz = st * rz[j];

        // h_k = r2 - pcx_k^2 - pcz_k^2 is quadratic in k:
        //   h += u1; u1 += u2
        const float dd = dx * dx + dz * dz;
        h[j]  = r2 - X0 * X0 - Z0 * Z0;
        u1[j] = 2.0f * (X0 * dx + Z0 * dz) - dd;
        u2[j] = -2.0f * dd;
        // arg = K_LIGHT*sqrt(h) - K_LIGHT*pcy; nkp = -K_LIGHT*pcy_k (linear)
        nkp[j] = -K_LIGHT * Y0;
        dnk[j] = K_LIGHT * dy;

        acc[j] = 0.0f; nsf[j] = nf; stp[j] = st; nsv[j] = ns; hit[j] = hj;
    }

    // Fused march: 4 independent MUFU chains per iteration.
    // Sample points are strictly inside the sphere => lhit always true
    // analytically; fmaxf(h,0) only guards fp noise at grazing rays.
    for (float kf = 0.0f; kf < maxns; kf += 1.0f) {
        #pragma unroll
        for (int j = 0; j < 4; j++) {
            const float sq = fsqrt_approx(fmaxf(h[j], 0.0f));
            const float e = fexp2_approx(fmaf(K_LIGHT, sq, nkp[j]));
            if (kf < nsf[j]) acc[j] += e;
            h[j] += u1[j]; u1[j] += u2[j]; nkp[j] += dnk[j];
        }
    }

    // Epilogue: T = exp2(K_SIGMA*step*ns), R = 0.6*step*T*exp2(K_SIGMA*step)*acc
    float T[4], R[4];
    #pragma unroll
    for (int j = 0; j < 4; j++) {
        const float ks = K_SIGMA * stp[j];
        const float Tj = fexp2_approx(ks * nsv[j]);
        const float Rj = 0.6f * stp[j] * Tj * fexp2_approx(ks) * acc[j];
        T[j] = hit[j] ? Tj : 1.0f;
        R[j] = hit[j] ? Rj : 0.0f;
    }

    // color = BG*T + LIGHT*R; BG=(0.572,0.772,0.921), LIGHT=(1.3,0.3,0.9)
    float4 o0, o1, o2;
    o0.x = 0.572f * T[0] + 1.3f * R[0];
    o0.y = 0.772f * T[0] + 0.3f * R[0];
    o0.z = 0.921f * T[0] + 0.9f * R[0];
    o0.w = 0.572f * T[1] + 1.3f * R[1];
    o1.x = 0.772f * T[1] + 0.3f * R[1];
    o1.y = 0.921f * T[1] + 0.9f * R[1];
    o1.z = 0.572f * T[2] + 1.3f * R[2];
    o1.w = 0.772f * T[2] + 0.3f * R[2];
    o2.x = 0.921f * T[2] + 0.9f * R[2];
    o2.y = 0.572f * T[3] + 1.3f * R[3];
    o2.z = 0.772f * T[3] + 0.3f * R[3];
    o2.w = 0.921f * T[3] + 0.9f * R[3];

    out4[3 * t + 0] = o0;
    out4[3 * t + 1] = o1;
    out4[3 * t + 2] = o2;
}

extern "C" void kernel_launch(void* const* d_in, const int* in_sizes, int n_in,
                              void* d_out, int out_size) {
    const float* scene = (const float*)d_in[0];
    const float4* dirs4 = (const float4*)d_in[1];
    float4* out4 = (float4*)d_out;
    const int npix = in_sizes[1] / 3;
    const int nthreads = npix / 4;
    const int threads = 128;
    const int blocks = (nthreads + threads - 1) / threads;
    raymarch_kernel<<<blocks, threads>>>(scene, dirs4, out4, nthreads);
}

// round 9
// speedup vs baseline: 1.0058x; 1.0058x over previous
#include <cuda_runtime.h>

// Ray-marched volumetric sphere, 1024x1024 pixels, 4 pixels/thread,
// fused 4-wide march loop, branch-free miss handling (seg clamp).
// in[0] = scene (4 f32: cx, cy, cz, radius)
// in[1] = dirs  (1024*1024*3 f32, normalized)
// out   = pixels (1024*1024*3 f32)

#define LOG2E    1.4426950408889634f
#define K_LIGHT  (-1.2f * LOG2E)   // exp2 coeff: DENSITY*(SCAT+ABS) = 1.2
#define K_SIGMA  (-0.6f * LOG2E)   // exp2 coeff: SIGMA = 0.6

__device__ __forceinline__ float fsqrt_approx(float x) {
    float r; asm("sqrt.approx.f32 %0, %1;" : "=f"(r) : "f"(x)); return r;
}
__device__ __forceinline__ float fexp2_approx(float x) {
    float r; asm("ex2.approx.f32 %0, %1;" : "=f"(r) : "f"(x)); return r;
}

__global__ __launch_bounds__(128, 12) void raymarch_kernel(
    const float* __restrict__ scene,
    const float4* __restrict__ dirs4,
    float4* __restrict__ out4,
    int nthreads)
{
    const int t = blockIdx.x * 128 + threadIdx.x;
    if (t >= nthreads) return;

    const float cx = __ldg(scene + 0);
    const float cy = __ldg(scene + 1);
    const float cz = __ldg(scene + 2);
    const float radius = __ldg(scene + 3);
    const float r2 = radius * radius;

    // RO = (0,0,3)
    const float ocx = -cx, ocy = -cy, ocz = 3.0f - cz;
    const float c0 = ocx * ocx + ocy * ocy + ocz * ocz - r2;

    const float4 d0 = dirs4[3 * t + 0];
    const float4 d1 = dirs4[3 * t + 1];
    const float4 d2 = dirs4[3 * t + 2];

    const float rx[4] = {d0.x, d0.w, d1.z, d2.y};
    const float ry[4] = {d0.y, d1.x, d1.w, d2.z};
    const float rz[4] = {d0.z, d1.y, d2.x, d2.w};

    // Per-pixel march state (second-difference recurrences) + epilogue state.
    float h[4], u1[4], u2[4], nkp[4], dnk[4], acc[4], nsf[4], stp[4], sgl[4];
    float maxns = 0.0f;

    #pragma unroll
    for (int j = 0; j < 4; j++) {
        // |rd| == 1: half-b quadratic.  x = -hb +- sqrt(hb^2 - c0)
        const float hb = rx[j] * ocx + ry[j] * ocy + rz[j] * ocz;
        const float disc = hb * hb - c0;
        const float sq = fsqrt_approx(fmaxf(disc, 0.0f));
        const float x2 = sq - hb;

        // Branch-free miss: for disc<0 (sq=0) or x2<0 this clamps to seg=0
        // -> ns=0, step=0 -> T=1, R=0 (the background path).
        const float t0 = fmaxf(-sq - hb, 0.0f);
        const float seg = fmaxf(x2 - t0, 0.0f);
        const float ns = ceilf(seg * 5.0f);            // seg / 0.2
        const float st = __fdividef(seg, fmaxf(ns, 1.0f));
        const float nf = fminf(ns, 12.0f);
        maxns = fmaxf(maxns, nf);

        // pc at k=0: oc + (x2 - 0.5*st)*rd; per-step delta = st*rd (backwards)
        const float ti = x2 - 0.5f * st;
        const float X0 = ocx + ti * rx[j];
        const float Y0 = ocy + ti * ry[j];
        const float Z0 = ocz + ti * rz[j];
        const float dx = st * rx[j], dy = st * ry[j], dz = st * rz[j];

        // h_k = r2 - pcx_k^2 - pcz_k^2 (quadratic in k): h += u1; u1 += u2
        const float dd = dx * dx + dz * dz;
        h[j]  = r2 - X0 * X0 - Z0 * Z0;
        u1[j] = 2.0f * (X0 * dx + Z0 * dz) - dd;
        u2[j] = -2.0f * dd;
        // exp2 arg = K_LIGHT*sqrt(h) + nkp;  nkp = -K_LIGHT*pcy_k (linear in k)
        nkp[j] = -K_LIGHT * Y0;
        dnk[j] = K_LIGHT * dy;

        acc[j] = 0.0f; nsf[j] = nf; stp[j] = st; sgl[j] = seg;
    }

    // Fused march: 4 independent MUFU chains per iteration.
    // Sample points lie strictly inside the sphere => light-ray always hits
    // (lhit true); fmaxf(h,0) only guards fp noise at grazing rays.
    for (float kf = 0.0f; kf < maxns; kf += 1.0f) {
        #pragma unroll
        for (int j = 0; j < 4; j++) {
            const float sq = fsqrt_approx(fmaxf(h[j], 0.0f));
            const float e = fexp2_approx(fmaf(K_LIGHT, sq, nkp[j]));
            if (kf < nsf[j]) acc[j] += e;
            h[j] += u1[j]; u1[j] += u2[j]; nkp[j] += dnk[j];
        }
    }

    // Epilogue: step*ns == seg (exact for ns>=1; seg=0 for miss), so
    //   T = exp2(K_SIGMA*seg);  R = 0.6*step * T * exp2(K_SIGMA*step) * acc
    float T[4], R[4];
    #pragma unroll
    for (int j = 0; j < 4; j++) {
        T[j] = fexp2_approx(K_SIGMA * sgl[j]);
        R[j] = 0.6f * stp[j] * T[j] * fexp2_approx(K_SIGMA * stp[j]) * acc[j];
    }

    // color = BG*T + LIGHT*R; BG=(0.572,0.772,0.921), LIGHT=(1.3,0.3,0.9)
    float4 o0, o1, o2;
    o0.x = 0.572f * T[0] + 1.3f * R[0];
    o0.y = 0.772f * T[0] + 0.3f * R[0];
    o0.z = 0.921f * T[0] + 0.9f * R[0];
    o0.w = 0.572f * T[1] + 1.3f * R[1];
    o1.x = 0.772f * T[1] + 0.3f * R[1];
    o1.y = 0.921f * T[1] + 0.9f * R[1];
    o1.z = 0.572f * T[2] + 1.3f * R[2];
    o1.w = 0.772f * T[2] + 0.3f * R[2];
    o2.x = 0.921f * T[2] + 0.9f * R[2];
    o2.y = 0.572f * T[3] + 1.3f * R[3];
    o2.z = 0.772f * T[3] + 0.3f * R[3];
    o2.w = 0.921f * T[3] + 0.9f * R[3];

    out4[3 * t + 0] = o0;
    out4[3 * t + 1] = o1;
    out4[3 * t + 2] = o2;
}

extern "C" void kernel_launch(void* const* d_in, const int* in_sizes, int n_in,
                              void* d_out, int out_size) {
    const float* scene = (const float*)d_in[0];
    const float4* dirs4 = (const float4*)d_in[1];
    float4* out4 = (float4*)d_out;
    const int npix = in_sizes[1] / 3;
    const int nthreads = npix / 4;
    const int threads = 128;
    const int blocks = (nthreads + threads - 1) / threads;
    raymarch_kernel<<<blocks, threads>>>(scene, dirs4, out4, nthreads);
}

// round 10
// speedup vs baseline: 1.0269x; 1.0209x over previous
#include <cuda_runtime.h>

// Ray-marched volumetric sphere, 1024x1024 pixels, 4 pixels/thread.
// Fused 4-wide march, second-difference recurrences, warp-coherent
// all-miss early-out.
// in[0] = scene (4 f32: cx, cy, cz, radius)
// in[1] = dirs  (1024*1024*3 f32, normalized)
// out   = pixels (1024*1024*3 f32)

#define LOG2E    1.4426950408889634f
#define K_LIGHT  (-1.2f * LOG2E)   // exp2 coeff: DENSITY*(SCAT+ABS) = 1.2
#define K_SIGMA  (-0.6f * LOG2E)   // exp2 coeff: SIGMA = 0.6

__device__ __forceinline__ float fsqrt_approx(float x) {
    float r; asm("sqrt.approx.f32 %0, %1;" : "=f"(r) : "f"(x)); return r;
}
__device__ __forceinline__ float fexp2_approx(float x) {
    float r; asm("ex2.approx.f32 %0, %1;" : "=f"(r) : "f"(x)); return r;
}

__global__ __launch_bounds__(128) void raymarch_kernel(
    const float* __restrict__ scene,
    const float4* __restrict__ dirs4,
    float4* __restrict__ out4,
    int nthreads)
{
    const int t = blockIdx.x * 128 + threadIdx.x;
    if (t >= nthreads) return;

    const float cx = __ldg(scene + 0);
    const float cy = __ldg(scene + 1);
    const float cz = __ldg(scene + 2);
    const float radius = __ldg(scene + 3);
    const float r2 = radius * radius;

    // RO = (0,0,3)
    const float ocx = -cx, ocy = -cy, ocz = 3.0f - cz;
    const float c0 = ocx * ocx + ocy * ocy + ocz * ocz - r2;

    const float4 d0 = dirs4[3 * t + 0];
    const float4 d1 = dirs4[3 * t + 1];
    const float4 d2 = dirs4[3 * t + 2];

    const float rx[4] = {d0.x, d0.w, d1.z, d2.y};
    const float ry[4] = {d0.y, d1.x, d1.w, d2.z};
    const float rz[4] = {d0.z, d1.y, d2.x, d2.w};

    // ---- Cheap hit test for all 4 pixels (|rd| == 1, half-b form) ----
    float hbv[4], sqv[4], x2v[4];
    bool anyhit = false;
    #pragma unroll
    for (int j = 0; j < 4; j++) {
        const float hb = rx[j] * ocx + ry[j] * ocy + rz[j] * ocz;
        const float disc = hb * hb - c0;
        const float sq = fsqrt_approx(fmaxf(disc, 0.0f));
        const float x2 = sq - hb;
        hbv[j] = hb; sqv[j] = sq; x2v[j] = x2;
        anyhit |= (disc >= 0.0f) && (x2 >= 0.0f);
    }

    // Warp-coherent early-out: all 4 pixels are background.
    if (!anyhit) {
        out4[3 * t + 0] = make_float4(0.572f, 0.772f, 0.921f, 0.572f);
        out4[3 * t + 1] = make_float4(0.772f, 0.921f, 0.572f, 0.772f);
        out4[3 * t + 2] = make_float4(0.921f, 0.572f, 0.772f, 0.921f);
        return;
    }

    // ---- Full march setup (miss lanes flow through with seg = 0) ----
    float h[4], u1[4], u2[4], nkp[4], dnk[4], acc[4], nsf[4], stp[4], sgl[4];
    float maxns = 0.0f;

    #pragma unroll
    for (int j = 0; j < 4; j++) {
        const float hb = hbv[j], sq = sqv[j], x2 = x2v[j];
        // For a miss (disc<0 => sq=0, or x2<0) this clamps to seg=0
        // -> ns=0, step=0 -> T=1, R=0: the background path, branch-free.
        const float t0 = fmaxf(-sq - hb, 0.0f);
        const float seg = fmaxf(x2 - t0, 0.0f);
        const float ns = ceilf(seg * 5.0f);            // seg / 0.2
        const float st = __fdividef(seg, fmaxf(ns, 1.0f));
        const float nf = fminf(ns, 12.0f);
        maxns = fmaxf(maxns, nf);

        // pc at k=0: oc + (x2 - 0.5*st)*rd; per-step delta = st*rd (backwards)
        const float ti = x2 - 0.5f * st;
        const float X0 = ocx + ti * rx[j];
        const float Y0 = ocy + ti * ry[j];
        const float Z0 = ocz + ti * rz[j];
        const float dx = st * rx[j], dy = st * ry[j], dz = st * rz[j];

        // h_k = r2 - pcx_k^2 - pcz_k^2 (quadratic in k): h += u1; u1 += u2
        const float dd = dx * dx + dz * dz;
        h[j]  = r2 - X0 * X0 - Z0 * Z0;
        u1[j] = 2.0f * (X0 * dx + Z0 * dz) - dd;
        u2[j] = -2.0f * dd;
        // exp2 arg = K_LIGHT*sqrt(h) + nkp;  nkp = -K_LIGHT*pcy_k (linear in k)
        nkp[j] = -K_LIGHT * Y0;
        dnk[j] = K_LIGHT * dy;

        acc[j] = 0.0f; nsf[j] = nf; stp[j] = st; sgl[j] = seg;
    }

    // Fused march: 4 independent MUFU chains per iteration.
    // Sample points lie strictly inside the sphere => light ray always hits;
    // fmaxf(h,0) only guards fp noise at grazing rays.
    const int nit = (int)maxns;
    float kf = 0.0f;
    for (int it = 0; it < nit; it++, kf += 1.0f) {
        #pragma unroll
        for (int j = 0; j < 4; j++) {
            const float sq = fsqrt_approx(fmaxf(h[j], 0.0f));
            const float e = fexp2_approx(fmaf(K_LIGHT, sq, nkp[j]));
            if (kf < nsf[j]) acc[j] += e;
            h[j] += u1[j]; u1[j] += u2[j]; nkp[j] += dnk[j];
        }
    }

    // Epilogue: step*ns == seg exactly (seg=0 for miss), so
    //   T = exp2(K_SIGMA*seg);  R = 0.6*step * T * exp2(K_SIGMA*step) * acc
    float T[4], R[4];
    #pragma unroll
    for (int j = 0; j < 4; j++) {
        T[j] = fexp2_approx(K_SIGMA * sgl[j]);
        R[j] = 0.6f * stp[j] * T[j] * fexp2_approx(K_SIGMA * stp[j]) * acc[j];
    }

    // color = BG*T + LIGHT*R; BG=(0.572,0.772,0.921), LIGHT=(1.3,0.3,0.9)
    float4 o0, o1, o2;
    o0.x = 0.572f * T[0] + 1.3f * R[0];
    o0.y = 0.772f * T[0] + 0.3f * R[0];
    o0.z = 0.921f * T[0] + 0.9f * R[0];
    o0.w = 0.572f * T[1] + 1.3f * R[1];
    o1.x = 0.772f * T[1] + 0.3f * R[1];
    o1.y = 0.921f * T[1] + 0.9f * R[1];
    o1.z = 0.572f * T[2] + 1.3f * R[2];
    o1.w = 0.772f * T[2] + 0.3f * R[2];
    o2.x = 0.921f * T[2] + 0.9f * R[2];
    o2.y = 0.572f * T[3] + 1.3f * R[3];
    o2.z = 0.772f * T[3] + 0.3f * R[3];
    o2.w = 0.921f * T[3] + 0.9f * R[3];

    out4[3 * t + 0] = o0;
    out4[3 * t + 1] = o1;
    out4[3 * t + 2] = o2;
}

extern "C" void kernel_launch(void* const* d_in, const int* in_sizes, int n_in,
                              void* d_out, int out_size) {
    const float* scene = (const float*)d_in[0];
    const float4* dirs4 = (const float4*)d_in[1];
    float4* out4 = (float4*)d_out;
    const int npix = in_sizes[1] / 3;
    const int nthreads = npix / 4;
    const int threads = 128;
    const int blocks = (nthreads + threads - 1) / threads;
    raymarch_kernel<<<blocks, threads>>>(scene, dirs4, out4, nthreads);
}